// round 2
// baseline (speedup 1.0000x reference)
#include <cuda_runtime.h>
#include <cuda_bf16.h>
#include <math.h>

// Problem constants (fixed-shape problem; runtime values read from in_sizes as a guard)
#define MAXN 100000
#define D 64
#define K_TOT 194      // S_in(64) | S_out(64) | hidden(64) | s_in(1) | s_out(1)
#define K_PAD 208      // padded to multiple of 16 (zero rows)
#define C_TOT 256      // cols: [0:64) r-sum, [64:128) i-sum, [128:192) i_n, [192:256) h_n
#define XSTRIDE 20     // smem row stride for Xs (16 nodes + pad, 16B aligned)

// ---------------- scratch (static device globals; no allocation) ----------------
__device__ float g_S[2 * (size_t)MAXN * D];   // scatter accumulators (raw hidden sums)
__device__ float g_s[2 * MAXN];               // edge-weight sums per dst
__device__ float g_M[K_PAD * C_TOT];          // fused weight matrix
__device__ float g_bias[C_TOT];               // fused bias

// ---------------- kernel 1: precompute fused matrix ----------------
// M rows: k<64: W_in @ W_ih[0:64,:]  (cols 0..191, else 0)
//         64<=k<128: W_out @ W_ih[64:128,:] (cols 0..191)
//         128<=k<192: W_hh row (r,i parts -> cols 0..127; n part -> cols 192..255)
//         k==192: b_in @ W_ih_top ; k==193: b_out @ W_ih_bot ; k>=194: zero
__global__ void precompute_kernel(const float* __restrict__ W_in, const float* __restrict__ b_in,
                                  const float* __restrict__ W_out, const float* __restrict__ b_out,
                                  const float* __restrict__ W_ih, const float* __restrict__ b_ih,
                                  const float* __restrict__ W_hh, const float* __restrict__ b_hh) {
    int k = blockIdx.x;       // 0..K_PAD-1
    int c = threadIdx.x;      // 0..255
    float v = 0.f;
    if (k < 64) {
        if (c < 192) {
            float a = 0.f;
            #pragma unroll 8
            for (int t = 0; t < 64; t++) a += W_in[k * 64 + t] * W_ih[t * 192 + c];
            v = a;
        }
    } else if (k < 128) {
        if (c < 192) {
            int aa = k - 64;
            float a = 0.f;
            #pragma unroll 8
            for (int t = 0; t < 64; t++) a += W_out[aa * 64 + t] * W_ih[(64 + t) * 192 + c];
            v = a;
        }
    } else if (k < 192) {
        int aa = k - 128;
        if (c < 128) v = W_hh[aa * 192 + c];
        else if (c >= 192) v = W_hh[aa * 192 + 128 + (c - 192)];
    } else if (k == 192) {
        if (c < 192) {
            float a = 0.f;
            for (int t = 0; t < 64; t++) a += b_in[t] * W_ih[t * 192 + c];
            v = a;
        }
    } else if (k == 193) {
        if (c < 192) {
            float a = 0.f;
            for (int t = 0; t < 64; t++) a += b_out[t] * W_ih[(64 + t) * 192 + c];
            v = a;
        }
    }
    g_M[k * C_TOT + c] = v;
    if (k == 0) {
        float b;
        if (c < 128)      b = b_ih[c] + b_hh[c];
        else if (c < 192) b = b_ih[c];
        else              b = b_hh[c - 64];   // b_hh[128 + (c-192)]
        g_bias[c] = b;
    }
}

// ---------------- kernel 2: zero accumulators ----------------
__global__ void zero_kernel(int n) {
    long totS = 2L * n * D;        // floats (divisible by 4)
    long tots = 2L * n;
    long tid = (long)blockIdx.x * blockDim.x + threadIdx.x;
    long stride = (long)gridDim.x * blockDim.x;
    float4 z = make_float4(0.f, 0.f, 0.f, 0.f);
    float4* S4 = reinterpret_cast<float4*>(g_S);
    for (long i = tid; i < totS / 4; i += stride) S4[i] = z;
    long rem = tots / 4;           // g_s zero (pad handled scalar below)
    float4* s4 = reinterpret_cast<float4*>(g_s);
    for (long i = tid; i < rem; i += stride) s4[i] = z;
    for (long i = rem * 4 + tid; i < tots; i += stride) g_s[i] = 0.f;
}

// ---------------- kernel 3: edge scatter (both sets, blockIdx.y selects) ----------------
__global__ void scatter_kernel(const float4* __restrict__ h4,
                               const int* __restrict__ srcA, const int* __restrict__ dstA,
                               const float* __restrict__ wA,
                               const int* __restrict__ srcB, const int* __restrict__ dstB,
                               const float* __restrict__ wB,
                               int E, int n) {
    int set = blockIdx.y;
    const int*   src = set ? srcB : srcA;
    const int*   dst = set ? dstB : dstA;
    const float* wp  = set ? wB   : wA;
    float* S  = g_S + (size_t)set * n * D;
    float* sw = g_s + (size_t)set * n;

    int lane = threadIdx.x & 31;
    int wid  = (blockIdx.x * blockDim.x + threadIdx.x) >> 5;
    int nw   = (gridDim.x * blockDim.x) >> 5;

    for (long base = (long)wid * 32; base < E; base += (long)nw * 32) {
        long e = base + lane;
        int s = 0, d = 0; float w = 0.f;
        if (e < E) { s = src[e]; d = dst[e]; w = wp[e]; }
        int cnt = (int)min((long)32, (long)E - base);
        for (int j = 0; j < cnt; j += 2) {
            int jj = j + (lane >> 4);                   // half-warp pairs: 2 edges / iter
            float ww = __shfl_sync(0xffffffffu, w, jj);
            int   ss = __shfl_sync(0xffffffffu, s, jj);
            int   dd = __shfl_sync(0xffffffffu, d, jj);
            if (jj < cnt) {
                int l = lane & 15;
                float4 v = h4[(size_t)ss * 16 + l];     // 16 lanes x 16B = full 256B row
                float* p = S + (size_t)dd * D + l * 4;
                asm volatile("red.global.add.v4.f32 [%0], {%1,%2,%3,%4};"
                             :: "l"(p), "f"(v.x * ww), "f"(v.y * ww),
                                "f"(v.z * ww), "f"(v.w * ww) : "memory");
                if (l == 0)
                    asm volatile("red.global.add.f32 [%0], %1;"
                                 :: "l"(sw + dd), "f"(ww) : "memory");
            }
        }
    }
}

// ---------------- kernel 4: fused node GEMM + GRU ----------------
// CTA: 256 threads, 16 nodes. Out tile 16x256, per-thread 4 nodes x 4 cols.
__global__ __launch_bounds__(256) void node_kernel(const float* __restrict__ hidden,
                                                   float* __restrict__ out, int n_nodes) {
    __shared__ float Xs[K_PAD][XSTRIDE];   // transposed X: Xs[k][node]
    __shared__ float Ms[16][C_TOT];        // M row-chunk; reused as g-buffer in epilogue

    int tid = threadIdx.x;
    int node0 = blockIdx.x * 16;

    // ---- load X tile (transposed) ----
    {
        int g = tid >> 4;       // node 0..15
        int l = tid & 15;
        int n = node0 + g;
        bool nv = (n < n_nodes);
        const float* Sin  = g_S;
        const float* Sout = g_S + (size_t)n_nodes * D;
        for (int k = l; k < K_PAD; k += 16) {
            float v = 0.f;
            if (nv) {
                if (k < 64)        v = Sin[(size_t)n * D + k];
                else if (k < 128)  v = Sout[(size_t)n * D + (k - 64)];
                else if (k < 192)  v = hidden[(size_t)n * D + (k - 128)];
                else if (k == 192) v = g_s[n];
                else if (k == 193) v = g_s[n_nodes + n];
            }
            Xs[k][g] = v;
        }
    }

    int tc = tid & 63;   // col group: cols [tc*4, tc*4+4)
    int ng = tid >> 6;   // node group: nodes [ng*4, ng*4+4)

    float acc[4][4];
    {
        float4 bv = *reinterpret_cast<const float4*>(&g_bias[tc * 4]);
        #pragma unroll
        for (int i = 0; i < 4; i++) {
            acc[i][0] = bv.x; acc[i][1] = bv.y; acc[i][2] = bv.z; acc[i][3] = bv.w;
        }
    }

    // ---- main GEMM loop ----
    for (int kb = 0; kb < K_PAD; kb += 16) {
        __syncthreads();
        // stage 16 rows of M (4096 floats) into smem
        const float4* Mg = reinterpret_cast<const float4*>(&g_M[kb * C_TOT]);
        float4* Msv = reinterpret_cast<float4*>(&Ms[0][0]);
        #pragma unroll
        for (int j = 0; j < 4; j++) Msv[tid + j * 256] = Mg[tid + j * 256];
        __syncthreads();

        #pragma unroll
        for (int kk = 0; kk < 16; kk++) {
            float4 m = *reinterpret_cast<const float4*>(&Ms[kk][tc * 4]);
            float4 x = *reinterpret_cast<const float4*>(&Xs[kb + kk][ng * 4]);
            acc[0][0] += x.x * m.x; acc[0][1] += x.x * m.y; acc[0][2] += x.x * m.z; acc[0][3] += x.x * m.w;
            acc[1][0] += x.y * m.x; acc[1][1] += x.y * m.y; acc[1][2] += x.y * m.z; acc[1][3] += x.y * m.w;
            acc[2][0] += x.z * m.x; acc[2][1] += x.z * m.y; acc[2][2] += x.z * m.z; acc[2][3] += x.z * m.w;
            acc[3][0] += x.w * m.x; acc[3][1] += x.w * m.y; acc[3][2] += x.w * m.z; acc[3][3] += x.w * m.w;
        }
    }

    // ---- write g tile into smem (reuse Ms) ----
    __syncthreads();
    #pragma unroll
    for (int i = 0; i < 4; i++) {
        *reinterpret_cast<float4*>(&Ms[ng * 4 + i][tc * 4]) =
            make_float4(acc[i][0], acc[i][1], acc[i][2], acc[i][3]);
    }
    __syncthreads();

    // ---- GRU epilogue: 16 nodes x 64 dims = 1024 outputs, 4 per thread ----
    #pragma unroll
    for (int j = 0; j < 4; j++) {
        int o = tid + j * 256;
        int i = o >> 6;
        int a = o & 63;
        int n = node0 + i;
        if (n < n_nodes) {
            float gr = Ms[i][a];
            float gi = Ms[i][64 + a];
            float g_in = Ms[i][128 + a];
            float g_hn = Ms[i][192 + a];
            float r  = 1.f / (1.f + expf(-gr));
            float ig = 1.f / (1.f + expf(-gi));
            float newg = tanhf(g_in + r * g_hn);
            float h = hidden[(size_t)n * D + a];
            out[(size_t)n * D + a] = (1.f - ig) * h + ig * newg;
        }
    }
}

// ---------------- launch ----------------
extern "C" void kernel_launch(void* const* d_in, const int* in_sizes, int n_in,
                              void* d_out, int out_size) {
    const float* hidden  = (const float*)d_in[0];
    const int*   in_src  = (const int*)  d_in[1];
    const int*   in_dst  = (const int*)  d_in[2];
    const float* in_w    = (const float*)d_in[3];
    const int*   out_src = (const int*)  d_in[4];
    const int*   out_dst = (const int*)  d_in[5];
    const float* out_w   = (const float*)d_in[6];
    const float* W_in    = (const float*)d_in[7];
    const float* b_in    = (const float*)d_in[8];
    const float* W_out   = (const float*)d_in[9];
    const float* b_out   = (const float*)d_in[10];
    const float* W_ih    = (const float*)d_in[11];
    const float* b_ih    = (const float*)d_in[12];
    const float* W_hh    = (const float*)d_in[13];
    const float* b_hh    = (const float*)d_in[14];
    float* out = (float*)d_out;

    int n = in_sizes[0] / D;
    if (n > MAXN) n = MAXN;        // defensive: scratch capacity
    int E = in_sizes[1];

    // 1. fused weight matrix (independent of scatter)
    precompute_kernel<<<K_PAD, C_TOT>>>(W_in, b_in, W_out, b_out, W_ih, b_ih, W_hh, b_hh);

    // 2. zero accumulators
    zero_kernel<<<1184, 256>>>(n);

    // 3. edge scatter, both sets
    if (E > 0) {
        dim3 grid(1184, 2);
        scatter_kernel<<<grid, 256>>>((const float4*)hidden,
                                      in_src, in_dst, in_w,
                                      out_src, out_dst, out_w, E, n);
    }

    // 4. fused GEMM + GRU
    node_kernel<<<(n + 15) / 16, 256>>>(hidden, out, n);
}

// round 5
// speedup vs baseline: 1.1228x; 1.1228x over previous
#include <cuda_runtime.h>
#include <cuda_bf16.h>
#include <math.h>

#define MAXN 100000
#define D 64
#define K_TOT 194      // S_in(64) | S_out(64) | hidden(64) | s_in(1) | s_out(1)
#define K_PAD 208      // padded to multiple of 16 (zero rows)
#define C_TOT 256      // cols: [0:64) r-sum, [64:128) i-sum, [128:192) i_n, [192:256) h_n
#define NODES_PER_CTA 32
#define XSTRIDE 36     // smem row stride for Xs (32 nodes + 4 pad)

// ---------------- scratch (static device globals; no allocation) ----------------
__device__ float g_S[2 * (size_t)MAXN * D];   // scatter accumulators (raw hidden sums)
__device__ float g_s[2 * MAXN];               // edge-weight sums per dst
__device__ float g_M[K_PAD * C_TOT];          // fused weight matrix
__device__ float g_bias[C_TOT];               // fused bias

// ---------------- kernel 1: precompute fused matrix ----------------
__global__ void precompute_kernel(const float* __restrict__ W_in, const float* __restrict__ b_in,
                                  const float* __restrict__ W_out, const float* __restrict__ b_out,
                                  const float* __restrict__ W_ih, const float* __restrict__ b_ih,
                                  const float* __restrict__ W_hh, const float* __restrict__ b_hh) {
    int k = blockIdx.x;       // 0..K_PAD-1
    int c = threadIdx.x;      // 0..255
    float v = 0.f;
    if (k < 64) {
        if (c < 192) {
            float a = 0.f;
            #pragma unroll 8
            for (int t = 0; t < 64; t++) a += W_in[k * 64 + t] * W_ih[t * 192 + c];
            v = a;
        }
    } else if (k < 128) {
        if (c < 192) {
            int aa = k - 64;
            float a = 0.f;
            #pragma unroll 8
            for (int t = 0; t < 64; t++) a += W_out[aa * 64 + t] * W_ih[(64 + t) * 192 + c];
            v = a;
        }
    } else if (k < 192) {
        int aa = k - 128;
        if (c < 128) v = W_hh[aa * 192 + c];
        else if (c >= 192) v = W_hh[aa * 192 + 128 + (c - 192)];
    } else if (k == 192) {
        if (c < 192) {
            float a = 0.f;
            for (int t = 0; t < 64; t++) a += b_in[t] * W_ih[t * 192 + c];
            v = a;
        }
    } else if (k == 193) {
        if (c < 192) {
            float a = 0.f;
            for (int t = 0; t < 64; t++) a += b_out[t] * W_ih[(64 + t) * 192 + c];
            v = a;
        }
    }
    g_M[k * C_TOT + c] = v;
    if (k == 0) {
        float b;
        if (c < 128)      b = b_ih[c] + b_hh[c];
        else if (c < 192) b = b_ih[c];
        else              b = b_hh[c - 64];   // b_hh[128 + (c-192)]
        g_bias[c] = b;
    }
}

// ---------------- kernel 2: zero accumulators ----------------
__global__ void zero_kernel(int n) {
    long totS = 2L * n * D;
    long tots = 2L * n;
    long tid = (long)blockIdx.x * blockDim.x + threadIdx.x;
    long stride = (long)gridDim.x * blockDim.x;
    float4 z = make_float4(0.f, 0.f, 0.f, 0.f);
    float4* S4 = reinterpret_cast<float4*>(g_S);
    for (long i = tid; i < totS / 4; i += stride) S4[i] = z;
    long rem = tots / 4;
    float4* s4 = reinterpret_cast<float4*>(g_s);
    for (long i = tid; i < rem; i += stride) s4[i] = z;
    for (long i = rem * 4 + tid; i < tots; i += stride) g_s[i] = 0.f;
}

// ---------------- kernel 3: edge scatter ----------------
__global__ void scatter_kernel(const float4* __restrict__ h4,
                               const int* __restrict__ srcA, const int* __restrict__ dstA,
                               const float* __restrict__ wA,
                               const int* __restrict__ srcB, const int* __restrict__ dstB,
                               const float* __restrict__ wB,
                               int E, int n) {
    int set = blockIdx.y;
    const int*   src = set ? srcB : srcA;
    const int*   dst = set ? dstB : dstA;
    const float* wp  = set ? wB   : wA;
    float* S  = g_S + (size_t)set * n * D;
    float* sw = g_s + (size_t)set * n;

    int lane = threadIdx.x & 31;
    int wid  = (blockIdx.x * blockDim.x + threadIdx.x) >> 5;
    int nw   = (gridDim.x * blockDim.x) >> 5;

    for (long base = (long)wid * 32; base < E; base += (long)nw * 32) {
        long e = base + lane;
        int s = 0, d = 0; float w = 0.f;
        if (e < E) { s = src[e]; d = dst[e]; w = wp[e]; }
        int cnt = (int)min((long)32, (long)E - base);
        for (int j = 0; j < cnt; j += 2) {
            int jj = j + (lane >> 4);                   // half-warp pairs: 2 edges / iter
            float ww = __shfl_sync(0xffffffffu, w, jj);
            int   ss = __shfl_sync(0xffffffffu, s, jj);
            int   dd = __shfl_sync(0xffffffffu, d, jj);
            if (jj < cnt) {
                int l = lane & 15;
                float4 v = h4[(size_t)ss * 16 + l];     // 16 lanes x 16B = full 256B row
                float* p = S + (size_t)dd * D + l * 4;
                asm volatile("red.global.add.v4.f32 [%0], {%1,%2,%3,%4};"
                             :: "l"(p), "f"(v.x * ww), "f"(v.y * ww),
                                "f"(v.z * ww), "f"(v.w * ww) : "memory");
                if (l == 0)
                    asm volatile("red.global.add.f32 [%0], %1;"
                                 :: "l"(sw + dd), "f"(ww) : "memory");
            }
        }
    }
}

// ---------------- kernel 4: fused node GEMM + GRU ----------------
// CTA: 256 threads, 32 nodes. Out tile 32x256, per-thread 8 nodes x 4 cols.
__global__ __launch_bounds__(256) void node_kernel(const float* __restrict__ hidden,
                                                   float* __restrict__ out, int n_nodes) {
    __shared__ float Xs[K_PAD][XSTRIDE];   // transposed X: Xs[k][node]
    __shared__ float Ms[16][C_TOT];        // M row-chunk; reused as g-buffer in epilogue

    int tid = threadIdx.x;
    int node0 = blockIdx.x * NODES_PER_CTA;

    // ---- load X tile (transposed): 8 threads per node ----
    {
        int g = tid >> 3;       // node 0..31
        int l = tid & 7;
        int n = node0 + g;
        bool nv = (n < n_nodes);
        const float* Sin  = g_S;
        const float* Sout = g_S + (size_t)n_nodes * D;
        for (int k = l; k < K_PAD; k += 8) {
            float v = 0.f;
            if (nv) {
                if (k < 64)        v = Sin[(size_t)n * D + k];
                else if (k < 128)  v = Sout[(size_t)n * D + (k - 64)];
                else if (k < 192)  v = hidden[(size_t)n * D + (k - 128)];
                else if (k == 192) v = g_s[n];
                else if (k == 193) v = g_s[n_nodes + n];
            }
            Xs[k][g] = v;
        }
    }

    int tc = tid & 63;   // col group: cols [tc*4, tc*4+4)
    int ng = tid >> 6;   // node group: nodes [ng*8, ng*8+8)

    float acc[8][4];
    {
        float4 bv = *reinterpret_cast<const float4*>(&g_bias[tc * 4]);
        #pragma unroll
        for (int i = 0; i < 8; i++) {
            acc[i][0] = bv.x; acc[i][1] = bv.y; acc[i][2] = bv.z; acc[i][3] = bv.w;
        }
    }

    // ---- main GEMM loop ----
    for (int kb = 0; kb < K_PAD; kb += 16) {
        __syncthreads();
        // stage 16 rows of M (4096 floats) into smem
        const float4* Mg = reinterpret_cast<const float4*>(&g_M[kb * C_TOT]);
        float4* Msv = reinterpret_cast<float4*>(&Ms[0][0]);
        #pragma unroll
        for (int j = 0; j < 4; j++) Msv[tid + j * 256] = Mg[tid + j * 256];
        __syncthreads();

        #pragma unroll
        for (int kk = 0; kk < 16; kk++) {
            float4 m  = *reinterpret_cast<const float4*>(&Ms[kk][tc * 4]);
            float4 xa = *reinterpret_cast<const float4*>(&Xs[kb + kk][ng * 8]);
            float4 xb = *reinterpret_cast<const float4*>(&Xs[kb + kk][ng * 8 + 4]);
            acc[0][0] += xa.x * m.x; acc[0][1] += xa.x * m.y; acc[0][2] += xa.x * m.z; acc[0][3] += xa.x * m.w;
            acc[1][0] += xa.y * m.x; acc[1][1] += xa.y * m.y; acc[1][2] += xa.y * m.z; acc[1][3] += xa.y * m.w;
            acc[2][0] += xa.z * m.x; acc[2][1] += xa.z * m.y; acc[2][2] += xa.z * m.z; acc[2][3] += xa.z * m.w;
            acc[3][0] += xa.w * m.x; acc[3][1] += xa.w * m.y; acc[3][2] += xa.w * m.z; acc[3][3] += xa.w * m.w;
            acc[4][0] += xb.x * m.x; acc[4][1] += xb.x * m.y; acc[4][2] += xb.x * m.z; acc[4][3] += xb.x * m.w;
            acc[5][0] += xb.y * m.x; acc[5][1] += xb.y * m.y; acc[5][2] += xb.y * m.z; acc[5][3] += xb.y * m.w;
            acc[6][0] += xb.z * m.x; acc[6][1] += xb.z * m.y; acc[6][2] += xb.z * m.z; acc[6][3] += xb.z * m.w;
            acc[7][0] += xb.w * m.x; acc[7][1] += xb.w * m.y; acc[7][2] += xb.w * m.z; acc[7][3] += xb.w * m.w;
        }
    }

    // ---- epilogue: two phases of 16 nodes through Ms, then GRU ----
    #pragma unroll
    for (int ph = 0; ph < 2; ph++) {
        __syncthreads();
        // node groups ng in {2*ph, 2*ph+1} write their 16x256 sub-tile
        if ((ng >> 1) == ph) {
            int nlocal = (ng & 1) * 8;   // 0 or 8 within this 16-node phase
            #pragma unroll
            for (int i = 0; i < 8; i++) {
                *reinterpret_cast<float4*>(&Ms[nlocal + i][tc * 4]) =
                    make_float4(acc[i][0], acc[i][1], acc[i][2], acc[i][3]);
            }
        }
        __syncthreads();
        // GRU on 16 nodes x 64 dims = 1024 outputs, 4 per thread
        #pragma unroll
        for (int j = 0; j < 4; j++) {
            int o = tid + j * 256;
            int i = o >> 6;              // local node 0..15
            int a = o & 63;              // dim
            int n = node0 + ph * 16 + i;
            if (n < n_nodes) {
                float gr   = Ms[i][a];
                float gi   = Ms[i][64 + a];
                float g_in = Ms[i][128 + a];
                float g_hn = Ms[i][192 + a];
                float r  = 1.f / (1.f + expf(-gr));
                float ig = 1.f / (1.f + expf(-gi));
                float newg = tanhf(g_in + r * g_hn);
                float h = hidden[(size_t)n * D + a];
                out[(size_t)n * D + a] = (1.f - ig) * h + ig * newg;
            }
        }
    }
}

// ---------------- launch ----------------
extern "C" void kernel_launch(void* const* d_in, const int* in_sizes, int n_in,
                              void* d_out, int out_size) {
    const float* hidden  = (const float*)d_in[0];
    const int*   in_src  = (const int*)  d_in[1];
    const int*   in_dst  = (const int*)  d_in[2];
    const float* in_w    = (const float*)d_in[3];
    const int*   out_src = (const int*)  d_in[4];
    const int*   out_dst = (const int*)  d_in[5];
    const float* out_w   = (const float*)d_in[6];
    const float* W_in    = (const float*)d_in[7];
    const float* b_in    = (const float*)d_in[8];
    const float* W_out   = (const float*)d_in[9];
    const float* b_out   = (const float*)d_in[10];
    const float* W_ih    = (const float*)d_in[11];
    const float* b_ih    = (const float*)d_in[12];
    const float* W_hh    = (const float*)d_in[13];
    const float* b_hh    = (const float*)d_in[14];
    float* out = (float*)d_out;

    int n = in_sizes[0] / D;
    if (n > MAXN) n = MAXN;
    int E = in_sizes[1];

    precompute_kernel<<<K_PAD, C_TOT>>>(W_in, b_in, W_out, b_out, W_ih, b_ih, W_hh, b_hh);
    zero_kernel<<<1184, 256>>>(n);
    if (E > 0) {
        dim3 grid(1184, 2);
        scatter_kernel<<<grid, 256>>>((const float4*)hidden,
                                      in_src, in_dst, in_w,
                                      out_src, out_dst, out_w, E, n);
    }
    node_kernel<<<(n + NODES_PER_CTA - 1) / NODES_PER_CTA, 256>>>(hidden, out, n);
}

// round 6
// speedup vs baseline: 1.1777x; 1.0489x over previous
#include <cuda_runtime.h>
#include <cuda_bf16.h>
#include <math.h>
#include <stdint.h>

#define MAXN 100000
#define D 64
#define K_PAD 208      // padded K (rows 194..207 zero)
#define C_TOT 256      // cols: [0:64) r, [64:128) i, [128:192) i_n, [192:256) h_n
#define NODES_PER_CTA 32
#define NCHUNK 25      // 8-row K-chunks 0..24 (rows 0..199); chunk 25 all-zero, skipped

// ---------------- scratch (static device globals; no allocation) ----------------
__device__ float g_S[2 * (size_t)MAXN * D];   // scatter accumulators (raw hidden sums)
__device__ float g_s[2 * MAXN];               // edge-weight sums per dst
__device__ float g_M[K_PAD * C_TOT];          // fused weight matrix
__device__ float g_bias[C_TOT];               // fused bias

// ---------------- kernel 1: precompute fused matrix ----------------
__global__ void precompute_kernel(const float* __restrict__ W_in, const float* __restrict__ b_in,
                                  const float* __restrict__ W_out, const float* __restrict__ b_out,
                                  const float* __restrict__ W_ih, const float* __restrict__ b_ih,
                                  const float* __restrict__ W_hh, const float* __restrict__ b_hh) {
    int k = blockIdx.x;       // 0..K_PAD-1
    int c = threadIdx.x;      // 0..255
    float v = 0.f;
    if (k < 64) {
        if (c < 192) {
            float a = 0.f;
            #pragma unroll 8
            for (int t = 0; t < 64; t++) a += W_in[k * 64 + t] * W_ih[t * 192 + c];
            v = a;
        }
    } else if (k < 128) {
        if (c < 192) {
            int aa = k - 64;
            float a = 0.f;
            #pragma unroll 8
            for (int t = 0; t < 64; t++) a += W_out[aa * 64 + t] * W_ih[(64 + t) * 192 + c];
            v = a;
        }
    } else if (k < 192) {
        int aa = k - 128;
        if (c < 128) v = W_hh[aa * 192 + c];
        else if (c >= 192) v = W_hh[aa * 192 + 128 + (c - 192)];
    } else if (k == 192) {
        if (c < 192) {
            float a = 0.f;
            for (int t = 0; t < 64; t++) a += b_in[t] * W_ih[t * 192 + c];
            v = a;
        }
    } else if (k == 193) {
        if (c < 192) {
            float a = 0.f;
            for (int t = 0; t < 64; t++) a += b_out[t] * W_ih[(64 + t) * 192 + c];
            v = a;
        }
    }
    g_M[k * C_TOT + c] = v;
    if (k == 0) {
        float b;
        if (c < 128)      b = b_ih[c] + b_hh[c];
        else if (c < 192) b = b_ih[c];
        else              b = b_hh[c - 64];   // b_hh[128 + (c-192)]
        g_bias[c] = b;
    }
}

// ---------------- kernel 2: zero accumulators ----------------
__global__ void zero_kernel(int n) {
    long totS = 2L * n * D;
    long tots = 2L * n;
    long tid = (long)blockIdx.x * blockDim.x + threadIdx.x;
    long stride = (long)gridDim.x * blockDim.x;
    float4 z = make_float4(0.f, 0.f, 0.f, 0.f);
    float4* S4 = reinterpret_cast<float4*>(g_S);
    for (long i = tid; i < totS / 4; i += stride) S4[i] = z;
    long rem = tots / 4;
    float4* s4 = reinterpret_cast<float4*>(g_s);
    for (long i = tid; i < rem; i += stride) s4[i] = z;
    for (long i = rem * 4 + tid; i < tots; i += stride) g_s[i] = 0.f;
}

// ---------------- kernel 3: edge scatter ----------------
__global__ void scatter_kernel(const float4* __restrict__ h4,
                               const int* __restrict__ srcA, const int* __restrict__ dstA,
                               const float* __restrict__ wA,
                               const int* __restrict__ srcB, const int* __restrict__ dstB,
                               const float* __restrict__ wB,
                               int E, int n) {
    int set = blockIdx.y;
    const int*   src = set ? srcB : srcA;
    const int*   dst = set ? dstB : dstA;
    const float* wp  = set ? wB   : wA;
    float* S  = g_S + (size_t)set * n * D;
    float* sw = g_s + (size_t)set * n;

    int lane = threadIdx.x & 31;
    int wid  = (blockIdx.x * blockDim.x + threadIdx.x) >> 5;
    int nw   = (gridDim.x * blockDim.x) >> 5;

    for (long base = (long)wid * 32; base < E; base += (long)nw * 32) {
        long e = base + lane;
        int s = 0, d = 0; float w = 0.f;
        if (e < E) { s = src[e]; d = dst[e]; w = wp[e]; }
        int cnt = (int)min((long)32, (long)E - base);
        for (int j = 0; j < cnt; j += 2) {
            int jj = j + (lane >> 4);                   // half-warp pairs: 2 edges / iter
            float ww = __shfl_sync(0xffffffffu, w, jj);
            int   ss = __shfl_sync(0xffffffffu, s, jj);
            int   dd = __shfl_sync(0xffffffffu, d, jj);
            if (jj < cnt) {
                int l = lane & 15;
                float4 v = h4[(size_t)ss * 16 + l];     // 16 lanes x 16B = full 256B row
                float* p = S + (size_t)dd * D + l * 4;
                asm volatile("red.global.add.v4.f32 [%0], {%1,%2,%3,%4};"
                             :: "l"(p), "f"(v.x * ww), "f"(v.y * ww),
                                "f"(v.z * ww), "f"(v.w * ww) : "memory");
                if (l == 0)
                    asm volatile("red.global.add.f32 [%0], %1;"
                                 :: "l"(sw + dd), "f"(ww) : "memory");
            }
        }
    }
}

// ---------------- kernel 4: fused node GEMM + GRU (sparsity-aware, cp.async) ----------------
// 256 threads, 32 nodes/CTA. Thread owns 8 nodes x 4 cols inside ONE gate quadrant:
//   q   = tid>>6        (quadrant: 0=r, 1=i, 2=i_n, 3=h_n; warp-uniform)
//   tcl = tid&15        (col group within quadrant -> cols q*64 + tcl*4 .. +4)
//   ng  = (tid>>4)&3    (node group -> nodes ng*8 .. +8)
// K-chunk activity (8-row chunks): q0/q1: 0..24; q2: 0..15 and 24; q3: 16..23.
__global__ __launch_bounds__(256, 4) void node_kernel(const float* __restrict__ hidden,
                                                      float* __restrict__ out, int n_nodes) {
    __shared__ float Xs[K_PAD][32];        // transposed X: Xs[k][node]  (26.6 KB)
    __shared__ float Ms[2][8][C_TOT];      // double-buffered M chunk    (16 KB)

    int tid = threadIdx.x;
    int node0 = blockIdx.x * NODES_PER_CTA;

    uint32_t ms_smem = (uint32_t)__cvta_generic_to_shared(&Ms[0][0][0]);

    // ---- issue cp.async for chunk 0 into buf 0 ----
    {
        const char* src = (const char*)(g_M) + (size_t)tid * 16;
        uint32_t dst = ms_smem + tid * 16;
        asm volatile("cp.async.cg.shared.global [%0], [%1], 16;" :: "r"(dst), "l"(src));
        asm volatile("cp.async.cg.shared.global [%0], [%1], 16;" :: "r"(dst + 4096), "l"(src + 4096));
        asm volatile("cp.async.commit_group;");
    }

    // ---- load X tile (transposed): 8 threads per node ----
    {
        int g = tid >> 3;       // node 0..31
        int l = tid & 7;
        int n = node0 + g;
        bool nv = (n < n_nodes);
        const float* Sin  = g_S;
        const float* Sout = g_S + (size_t)n_nodes * D;
        #pragma unroll
        for (int k = l; k < K_PAD; k += 8) {
            float v = 0.f;
            if (nv) {
                if (k < 64)        v = Sin[(size_t)n * D + k];
                else if (k < 128)  v = Sout[(size_t)n * D + (k - 64)];
                else if (k < 192)  v = hidden[(size_t)n * D + (k - 128)];
                else if (k == 192) v = g_s[n];
                else if (k == 193) v = g_s[n_nodes + n];
            }
            Xs[k][g] = v;
        }
    }

    int q   = tid >> 6;
    int tcl = tid & 15;
    int ng  = (tid >> 4) & 3;
    int colb = q * 64 + tcl * 4;

    float acc[8][4];
    {
        float4 bv = *reinterpret_cast<const float4*>(&g_bias[colb]);
        #pragma unroll
        for (int i = 0; i < 8; i++) {
            acc[i][0] = bv.x; acc[i][1] = bv.y; acc[i][2] = bv.z; acc[i][3] = bv.w;
        }
    }

    asm volatile("cp.async.wait_group 0;" ::: "memory");
    __syncthreads();

    // ---- main GEMM loop over 25 chunks, cp.async double buffer ----
    int buf = 0;
    for (int c = 0; c < NCHUNK; c++) {
        if (c + 1 < NCHUNK) {
            const char* src = (const char*)(g_M) + (size_t)(c + 1) * 8192 + (size_t)tid * 16;
            uint32_t dst = ms_smem + (buf ^ 1) * 8192 + tid * 16;
            asm volatile("cp.async.cg.shared.global [%0], [%1], 16;" :: "r"(dst), "l"(src));
            asm volatile("cp.async.cg.shared.global [%0], [%1], 16;" :: "r"(dst + 4096), "l"(src + 4096));
            asm volatile("cp.async.commit_group;");
        }
        bool active = (q < 2) ? (true)
                    : (q == 2 ? (c < 16 || c == 24) : (c >= 16 && c < 24));
        if (active) {
            int kb = c * 8;
            #pragma unroll
            for (int kk = 0; kk < 8; kk++) {
                float4 m  = *reinterpret_cast<const float4*>(&Ms[buf][kk][colb]);
                float4 xa = *reinterpret_cast<const float4*>(&Xs[kb + kk][ng * 8]);
                float4 xb = *reinterpret_cast<const float4*>(&Xs[kb + kk][ng * 8 + 4]);
                acc[0][0] += xa.x * m.x; acc[0][1] += xa.x * m.y; acc[0][2] += xa.x * m.z; acc[0][3] += xa.x * m.w;
                acc[1][0] += xa.y * m.x; acc[1][1] += xa.y * m.y; acc[1][2] += xa.y * m.z; acc[1][3] += xa.y * m.w;
                acc[2][0] += xa.z * m.x; acc[2][1] += xa.z * m.y; acc[2][2] += xa.z * m.z; acc[2][3] += xa.z * m.w;
                acc[3][0] += xa.w * m.x; acc[3][1] += xa.w * m.y; acc[3][2] += xa.w * m.z; acc[3][3] += xa.w * m.w;
                acc[4][0] += xb.x * m.x; acc[4][1] += xb.x * m.y; acc[4][2] += xb.x * m.z; acc[4][3] += xb.x * m.w;
                acc[5][0] += xb.y * m.x; acc[5][1] += xb.y * m.y; acc[5][2] += xb.y * m.z; acc[5][3] += xb.y * m.w;
                acc[6][0] += xb.z * m.x; acc[6][1] += xb.z * m.y; acc[6][2] += xb.z * m.z; acc[6][3] += xb.z * m.w;
                acc[7][0] += xb.w * m.x; acc[7][1] += xb.w * m.y; acc[7][2] += xb.w * m.z; acc[7][3] += xb.w * m.w;
            }
        }
        asm volatile("cp.async.wait_group 0;" ::: "memory");
        __syncthreads();
        buf ^= 1;
    }

    // ---- epilogue: two phases of 16 nodes through Ms (16KB = [16][256]), then GRU ----
    float* Es = &Ms[0][0][0];
    #pragma unroll
    for (int ph = 0; ph < 2; ph++) {
        __syncthreads();
        if ((ng >> 1) == ph) {
            int nl = (ng & 1) * 8;
            #pragma unroll
            for (int i = 0; i < 8; i++) {
                *reinterpret_cast<float4*>(&Es[(nl + i) * C_TOT + colb]) =
                    make_float4(acc[i][0], acc[i][1], acc[i][2], acc[i][3]);
            }
        }
        __syncthreads();
        #pragma unroll
        for (int j = 0; j < 4; j++) {
            int o = tid + j * 256;
            int i = o >> 6;              // local node 0..15
            int a = o & 63;              // dim
            int n = node0 + ph * 16 + i;
            if (n < n_nodes) {
                float gr   = Es[i * C_TOT + a];
                float gi   = Es[i * C_TOT + 64 + a];
                float g_in = Es[i * C_TOT + 128 + a];
                float g_hn = Es[i * C_TOT + 192 + a];
                float r  = 1.f / (1.f + expf(-gr));
                float ig = 1.f / (1.f + expf(-gi));
                float newg = tanhf(g_in + r * g_hn);
                float h = hidden[(size_t)n * D + a];
                out[(size_t)n * D + a] = (1.f - ig) * h + ig * newg;
            }
        }
    }
}

// ---------------- launch ----------------
extern "C" void kernel_launch(void* const* d_in, const int* in_sizes, int n_in,
                              void* d_out, int out_size) {
    const float* hidden  = (const float*)d_in[0];
    const int*   in_src  = (const int*)  d_in[1];
    const int*   in_dst  = (const int*)  d_in[2];
    const float* in_w    = (const float*)d_in[3];
    const int*   out_src = (const int*)  d_in[4];
    const int*   out_dst = (const int*)  d_in[5];
    const float* out_w   = (const float*)d_in[6];
    const float* W_in    = (const float*)d_in[7];
    const float* b_in    = (const float*)d_in[8];
    const float* W_out   = (const float*)d_in[9];
    const float* b_out   = (const float*)d_in[10];
    const float* W_ih    = (const float*)d_in[11];
    const float* b_ih    = (const float*)d_in[12];
    const float* W_hh    = (const float*)d_in[13];
    const float* b_hh    = (const float*)d_in[14];
    float* out = (float*)d_out;

    int n = in_sizes[0] / D;
    if (n > MAXN) n = MAXN;
    int E = in_sizes[1];

    precompute_kernel<<<K_PAD, C_TOT>>>(W_in, b_in, W_out, b_out, W_ih, b_ih, W_hh, b_hh);
    zero_kernel<<<1184, 256>>>(n);
    if (E > 0) {
        dim3 grid(1184, 2);
        scatter_kernel<<<grid, 256>>>((const float4*)hidden,
                                      in_src, in_dst, in_w,
                                      out_src, out_dst, out_w, E, n);
    }
    node_kernel<<<(n + NODES_PER_CTA - 1) / NODES_PER_CTA, 256>>>(hidden, out, n);
}

// round 7
// speedup vs baseline: 1.2145x; 1.0312x over previous
#include <cuda_runtime.h>
#include <cuda_bf16.h>
#include <math.h>
#include <stdint.h>

#define MAXN 100000
#define D 64
#define K_PAD 208
#define C_TOT 256      // cols: [0:64) r, [64:128) i, [128:192) i_n, [192:256) h_n
#define TILE_N 64      // nodes per tile
#define NTHREADS 512
#define GRID_SM 148
#define XSTR 68        // Xs row stride (64 nodes + 4 pad, conflict-free build)

// smem partition (floats):
//  Mg [194][128] : 24832   gate cols 0-127, K rows 0-193
//  Mi [130][64]  : 8320    i_n cols 128-191, rows 0-127 then 192,193
//  Mh [64][64]   : 4096    h_n cols 192-255, rows 128-191
//  UB [16384]    : union — Xs[194][68] during mainloop, Epi[64][256] in epilogue
#define OFF_MG 0
#define OFF_MI 24832
#define OFF_MH 33152
#define OFF_UB 37248
#define SMEM_FLOATS 53632   // 214,528 bytes

// ---------------- scratch ----------------
__device__ float g_S[2 * (size_t)MAXN * D];
__device__ float g_s[2 * MAXN];
__device__ float g_M[K_PAD * C_TOT];
__device__ float g_bias[C_TOT];

// ---------------- kernel 1: precompute fused matrix ----------------
__global__ void precompute_kernel(const float* __restrict__ W_in, const float* __restrict__ b_in,
                                  const float* __restrict__ W_out, const float* __restrict__ b_out,
                                  const float* __restrict__ W_ih, const float* __restrict__ b_ih,
                                  const float* __restrict__ W_hh, const float* __restrict__ b_hh) {
    int k = blockIdx.x;
    int c = threadIdx.x;
    float v = 0.f;
    if (k < 64) {
        if (c < 192) {
            float a = 0.f;
            #pragma unroll 8
            for (int t = 0; t < 64; t++) a += W_in[k * 64 + t] * W_ih[t * 192 + c];
            v = a;
        }
    } else if (k < 128) {
        if (c < 192) {
            int aa = k - 64;
            float a = 0.f;
            #pragma unroll 8
            for (int t = 0; t < 64; t++) a += W_out[aa * 64 + t] * W_ih[(64 + t) * 192 + c];
            v = a;
        }
    } else if (k < 192) {
        int aa = k - 128;
        if (c < 128) v = W_hh[aa * 192 + c];
        else if (c >= 192) v = W_hh[aa * 192 + 128 + (c - 192)];
    } else if (k == 192) {
        if (c < 192) {
            float a = 0.f;
            for (int t = 0; t < 64; t++) a += b_in[t] * W_ih[t * 192 + c];
            v = a;
        }
    } else if (k == 193) {
        if (c < 192) {
            float a = 0.f;
            for (int t = 0; t < 64; t++) a += b_out[t] * W_ih[(64 + t) * 192 + c];
            v = a;
        }
    }
    g_M[k * C_TOT + c] = v;
    if (k == 0) {
        float b;
        if (c < 128)      b = b_ih[c] + b_hh[c];
        else if (c < 192) b = b_ih[c];
        else              b = b_hh[c - 64];
        g_bias[c] = b;
    }
}

// ---------------- kernel 2: zero accumulators ----------------
__global__ void zero_kernel(int n) {
    long totS = 2L * n * D;
    long tots = 2L * n;
    long tid = (long)blockIdx.x * blockDim.x + threadIdx.x;
    long stride = (long)gridDim.x * blockDim.x;
    float4 z = make_float4(0.f, 0.f, 0.f, 0.f);
    float4* S4 = reinterpret_cast<float4*>(g_S);
    for (long i = tid; i < totS / 4; i += stride) S4[i] = z;
    long rem = tots / 4;
    float4* s4 = reinterpret_cast<float4*>(g_s);
    for (long i = tid; i < rem; i += stride) s4[i] = z;
    for (long i = rem * 4 + tid; i < tots; i += stride) g_s[i] = 0.f;
}

// ---------------- kernel 3: edge scatter ----------------
__global__ void scatter_kernel(const float4* __restrict__ h4,
                               const int* __restrict__ srcA, const int* __restrict__ dstA,
                               const float* __restrict__ wA,
                               const int* __restrict__ srcB, const int* __restrict__ dstB,
                               const float* __restrict__ wB,
                               int E, int n) {
    int set = blockIdx.y;
    const int*   src = set ? srcB : srcA;
    const int*   dst = set ? dstB : dstA;
    const float* wp  = set ? wB   : wA;
    float* S  = g_S + (size_t)set * n * D;
    float* sw = g_s + (size_t)set * n;

    int lane = threadIdx.x & 31;
    int wid  = (blockIdx.x * blockDim.x + threadIdx.x) >> 5;
    int nw   = (gridDim.x * blockDim.x) >> 5;

    for (long base = (long)wid * 32; base < E; base += (long)nw * 32) {
        long e = base + lane;
        int s = 0, d = 0; float w = 0.f;
        if (e < E) { s = src[e]; d = dst[e]; w = wp[e]; }
        int cnt = (int)min((long)32, (long)E - base);
        for (int j = 0; j < cnt; j += 2) {
            int jj = j + (lane >> 4);
            float ww = __shfl_sync(0xffffffffu, w, jj);
            int   ss = __shfl_sync(0xffffffffu, s, jj);
            int   dd = __shfl_sync(0xffffffffu, d, jj);
            if (jj < cnt) {
                int l = lane & 15;
                float4 v = h4[(size_t)ss * 16 + l];
                float* p = S + (size_t)dd * D + l * 4;
                asm volatile("red.global.add.v4.f32 [%0], {%1,%2,%3,%4};"
                             :: "l"(p), "f"(v.x * ww), "f"(v.y * ww),
                                "f"(v.z * ww), "f"(v.w * ww) : "memory");
                if (l == 0)
                    asm volatile("red.global.add.f32 [%0], %1;"
                                 :: "l"(sw + dd), "f"(ww) : "memory");
            }
        }
    }
}

// ---------------- kernel 4: persistent fused node GEMM + GRU ----------------
// 148 CTAs x 512 threads, M resident in smem, 64-node tiles, barrier-free K-loop.
// Warps 0-7: gate cols (K=194); 8-11: i_n (K=130); 12-15: h_n (K=64).
// Per-SMSP K-work: 194+194+130+64 = 582 (perfectly balanced).
extern __shared__ float smem[];

__global__ __launch_bounds__(NTHREADS, 1) void node_kernel(const float* __restrict__ hidden,
                                                           float* __restrict__ out,
                                                           int n_nodes, int ntiles) {
    float* Mg = smem + OFF_MG;   // [194][128]
    float* Mi = smem + OFF_MI;   // [130][64]
    float* Mh = smem + OFF_MH;   // [64][64]
    float* UB = smem + OFF_UB;   // Xs[194][68] / Epi[64][256]

    int tid = threadIdx.x;

    // ---- load M panels once (float4 granularity) ----
    {
        float4* Mg4 = reinterpret_cast<float4*>(Mg);
        for (int i = tid; i < 194 * 32; i += NTHREADS) {       // gates: rows 0-193, cols 0-127
            int r = i >> 5, c4 = i & 31;
            Mg4[i] = *reinterpret_cast<const float4*>(&g_M[r * C_TOT + c4 * 4]);
        }
        float4* Mi4 = reinterpret_cast<float4*>(Mi);
        for (int i = tid; i < 130 * 16; i += NTHREADS) {       // i_n: rows 0-127,192,193; cols 128-191
            int r = i >> 4, c4 = i & 15;
            int gr = (r < 128) ? r : (192 + (r - 128));
            Mi4[i] = *reinterpret_cast<const float4*>(&g_M[gr * C_TOT + 128 + c4 * 4]);
        }
        float4* Mh4 = reinterpret_cast<float4*>(Mh);
        for (int i = tid; i < 64 * 16; i += NTHREADS) {        // h_n: rows 128-191; cols 192-255
            int r = i >> 4, c4 = i & 15;
            Mh4[i] = *reinterpret_cast<const float4*>(&g_M[(128 + r) * C_TOT + 192 + c4 * 4]);
        }
    }
    __syncthreads();

    const float* Sin  = g_S;
    const float* Sout = g_S + (size_t)n_nodes * D;

    for (int tile = blockIdx.x; tile < ntiles; tile += gridDim.x) {
        int node0 = tile * TILE_N;

        // ---- build X tile: Xs[k][node], 8 threads per node ----
        {
            int g = tid >> 3;       // node 0..63
            int l = tid & 7;
            int n = node0 + g;
            bool nv = (n < n_nodes);
            #pragma unroll
            for (int k = l; k < 194; k += 8) {
                float v = 0.f;
                if (nv) {
                    if (k < 64)        v = Sin[(size_t)n * D + k];
                    else if (k < 128)  v = Sout[(size_t)n * D + (k - 64)];
                    else if (k < 192)  v = hidden[(size_t)n * D + (k - 128)];
                    else if (k == 192) v = g_s[n];
                    else               v = g_s[n_nodes + n];
                }
                UB[k * XSTR + g] = v;
            }
        }
        __syncthreads();

        // ---- barrier-free GEMM: each warp-class loops its own K range ----
        float acc[8][4];
        int wid = tid >> 5;

        if (wid < 8) {
            // gates: cols 0-127, K=0..193
            int tcl = tid & 31;          // col quad 0..31 -> cols tcl*4
            int ng  = tid >> 5;          // node group 0..7 (warp-uniform)
            float4 bv = *reinterpret_cast<const float4*>(&g_bias[tcl * 4]);
            #pragma unroll
            for (int i = 0; i < 8; i++) { acc[i][0]=bv.x; acc[i][1]=bv.y; acc[i][2]=bv.z; acc[i][3]=bv.w; }
            const float* xs = UB + ng * 8;
            const float* mp = Mg + tcl * 4;
            #pragma unroll 2
            for (int k = 0; k < 194; k++) {
                float4 m  = *reinterpret_cast<const float4*>(mp + k * 128);
                float4 xa = *reinterpret_cast<const float4*>(xs + k * XSTR);
                float4 xb = *reinterpret_cast<const float4*>(xs + k * XSTR + 4);
                acc[0][0]+=xa.x*m.x; acc[0][1]+=xa.x*m.y; acc[0][2]+=xa.x*m.z; acc[0][3]+=xa.x*m.w;
                acc[1][0]+=xa.y*m.x; acc[1][1]+=xa.y*m.y; acc[1][2]+=xa.y*m.z; acc[1][3]+=xa.y*m.w;
                acc[2][0]+=xa.z*m.x; acc[2][1]+=xa.z*m.y; acc[2][2]+=xa.z*m.z; acc[2][3]+=xa.z*m.w;
                acc[3][0]+=xa.w*m.x; acc[3][1]+=xa.w*m.y; acc[3][2]+=xa.w*m.z; acc[3][3]+=xa.w*m.w;
                acc[4][0]+=xb.x*m.x; acc[4][1]+=xb.x*m.y; acc[4][2]+=xb.x*m.z; acc[4][3]+=xb.x*m.w;
                acc[5][0]+=xb.y*m.x; acc[5][1]+=xb.y*m.y; acc[5][2]+=xb.y*m.z; acc[5][3]+=xb.y*m.w;
                acc[6][0]+=xb.z*m.x; acc[6][1]+=xb.z*m.y; acc[6][2]+=xb.z*m.z; acc[6][3]+=xb.z*m.w;
                acc[7][0]+=xb.w*m.x; acc[7][1]+=xb.w*m.y; acc[7][2]+=xb.w*m.z; acc[7][3]+=xb.w*m.w;
            }
        } else if (wid < 12) {
            // i_n: cols 128-191, rows 0..127 then 192,193 (Mi rows 128,129)
            int local = tid - 256;
            int tcl = local & 15;        // cols 128 + tcl*4
            int ng  = local >> 4;        // 0..7
            float4 bv = *reinterpret_cast<const float4*>(&g_bias[128 + tcl * 4]);
            #pragma unroll
            for (int i = 0; i < 8; i++) { acc[i][0]=bv.x; acc[i][1]=bv.y; acc[i][2]=bv.z; acc[i][3]=bv.w; }
            const float* xs = UB + ng * 8;
            const float* mp = Mi + tcl * 4;
            #pragma unroll 2
            for (int k = 0; k < 130; k++) {
                int xk = (k < 128) ? k : (64 + k);   // 128->192, 129->193
                float4 m  = *reinterpret_cast<const float4*>(mp + k * 64);
                float4 xa = *reinterpret_cast<const float4*>(xs + xk * XSTR);
                float4 xb = *reinterpret_cast<const float4*>(xs + xk * XSTR + 4);
                acc[0][0]+=xa.x*m.x; acc[0][1]+=xa.x*m.y; acc[0][2]+=xa.x*m.z; acc[0][3]+=xa.x*m.w;
                acc[1][0]+=xa.y*m.x; acc[1][1]+=xa.y*m.y; acc[1][2]+=xa.y*m.z; acc[1][3]+=xa.y*m.w;
                acc[2][0]+=xa.z*m.x; acc[2][1]+=xa.z*m.y; acc[2][2]+=xa.z*m.z; acc[2][3]+=xa.z*m.w;
                acc[3][0]+=xa.w*m.x; acc[3][1]+=xa.w*m.y; acc[3][2]+=xa.w*m.z; acc[3][3]+=xa.w*m.w;
                acc[4][0]+=xb.x*m.x; acc[4][1]+=xb.x*m.y; acc[4][2]+=xb.x*m.z; acc[4][3]+=xb.x*m.w;
                acc[5][0]+=xb.y*m.x; acc[5][1]+=xb.y*m.y; acc[5][2]+=xb.y*m.z; acc[5][3]+=xb.y*m.w;
                acc[6][0]+=xb.z*m.x; acc[6][1]+=xb.z*m.y; acc[6][2]+=xb.z*m.z; acc[6][3]+=xb.z*m.w;
                acc[7][0]+=xb.w*m.x; acc[7][1]+=xb.w*m.y; acc[7][2]+=xb.w*m.z; acc[7][3]+=xb.w*m.w;
            }
        } else {
            // h_n: cols 192-255, rows 128..191 (X rows 128+k)
            int local = tid - 384;
            int tcl = local & 15;
            int ng  = local >> 4;
            float4 bv = *reinterpret_cast<const float4*>(&g_bias[192 + tcl * 4]);
            #pragma unroll
            for (int i = 0; i < 8; i++) { acc[i][0]=bv.x; acc[i][1]=bv.y; acc[i][2]=bv.z; acc[i][3]=bv.w; }
            const float* xs = UB + ng * 8 + 128 * XSTR;
            const float* mp = Mh + tcl * 4;
            #pragma unroll 2
            for (int k = 0; k < 64; k++) {
                float4 m  = *reinterpret_cast<const float4*>(mp + k * 64);
                float4 xa = *reinterpret_cast<const float4*>(xs + k * XSTR);
                float4 xb = *reinterpret_cast<const float4*>(xs + k * XSTR + 4);
                acc[0][0]+=xa.x*m.x; acc[0][1]+=xa.x*m.y; acc[0][2]+=xa.x*m.z; acc[0][3]+=xa.x*m.w;
                acc[1][0]+=xa.y*m.x; acc[1][1]+=xa.y*m.y; acc[1][2]+=xa.y*m.z; acc[1][3]+=xa.y*m.w;
                acc[2][0]+=xa.z*m.x; acc[2][1]+=xa.z*m.y; acc[2][2]+=xa.z*m.z; acc[2][3]+=xa.z*m.w;
                acc[3][0]+=xa.w*m.x; acc[3][1]+=xa.w*m.y; acc[3][2]+=xa.w*m.z; acc[3][3]+=xa.w*m.w;
                acc[4][0]+=xb.x*m.x; acc[4][1]+=xb.x*m.y; acc[4][2]+=xb.x*m.z; acc[4][3]+=xb.x*m.w;
                acc[5][0]+=xb.y*m.x; acc[5][1]+=xb.y*m.y; acc[5][2]+=xb.y*m.z; acc[5][3]+=xb.y*m.w;
                acc[6][0]+=xb.z*m.x; acc[6][1]+=xb.z*m.y; acc[6][2]+=xb.z*m.z; acc[6][3]+=xb.z*m.w;
                acc[7][0]+=xb.w*m.x; acc[7][1]+=xb.w*m.y; acc[7][2]+=xb.w*m.z; acc[7][3]+=xb.w*m.w;
            }
        }
        __syncthreads();   // X no longer needed; UB becomes Epi

        // ---- write partials into Epi[64][256] ----
        {
            int colb, ng;
            if (wid < 8)       { colb = (tid & 31) * 4;           ng = tid >> 5; }
            else if (wid < 12) { colb = 128 + (tid & 15) * 4;     ng = (tid - 256) >> 4; }
            else               { colb = 192 + (tid & 15) * 4;     ng = (tid - 384) >> 4; }
            #pragma unroll
            for (int i = 0; i < 8; i++) {
                *reinterpret_cast<float4*>(&UB[(ng * 8 + i) * C_TOT + colb]) =
                    make_float4(acc[i][0], acc[i][1], acc[i][2], acc[i][3]);
            }
        }
        __syncthreads();

        // ---- GRU: 64 nodes x 64 dims = 4096 outputs, 8 per thread ----
        #pragma unroll
        for (int j = 0; j < 8; j++) {
            int o = tid + j * NTHREADS;
            int i = o >> 6;
            int a = o & 63;
            int n = node0 + i;
            if (n < n_nodes) {
                float gr   = UB[i * C_TOT + a];
                float gi   = UB[i * C_TOT + 64 + a];
                float g_in = UB[i * C_TOT + 128 + a];
                float g_hn = UB[i * C_TOT + 192 + a];
                float r  = 1.f / (1.f + expf(-gr));
                float ig = 1.f / (1.f + expf(-gi));
                float newg = tanhf(g_in + r * g_hn);
                float h = hidden[(size_t)n * D + a];
                out[(size_t)n * D + a] = (1.f - ig) * h + ig * newg;
            }
        }
        __syncthreads();   // protect UB before next tile's X build
    }
}

// ---------------- launch ----------------
extern "C" void kernel_launch(void* const* d_in, const int* in_sizes, int n_in,
                              void* d_out, int out_size) {
    const float* hidden  = (const float*)d_in[0];
    const int*   in_src  = (const int*)  d_in[1];
    const int*   in_dst  = (const int*)  d_in[2];
    const float* in_w    = (const float*)d_in[3];
    const int*   out_src = (const int*)  d_in[4];
    const int*   out_dst = (const int*)  d_in[5];
    const float* out_w   = (const float*)d_in[6];
    const float* W_in    = (const float*)d_in[7];
    const float* b_in    = (const float*)d_in[8];
    const float* W_out   = (const float*)d_in[9];
    const float* b_out   = (const float*)d_in[10];
    const float* W_ih    = (const float*)d_in[11];
    const float* b_ih    = (const float*)d_in[12];
    const float* W_hh    = (const float*)d_in[13];
    const float* b_hh    = (const float*)d_in[14];
    float* out = (float*)d_out;

    int n = in_sizes[0] / D;
    if (n > MAXN) n = MAXN;
    int E = in_sizes[1];

    precompute_kernel<<<K_PAD, C_TOT>>>(W_in, b_in, W_out, b_out, W_ih, b_ih, W_hh, b_hh);
    zero_kernel<<<1184, 256>>>(n);
    if (E > 0) {
        dim3 grid(1184, 2);
        scatter_kernel<<<grid, 256>>>((const float4*)hidden,
                                      in_src, in_dst, in_w,
                                      out_src, out_dst, out_w, E, n);
    }

    int ntiles = (n + TILE_N - 1) / TILE_N;
    int grid_n = ntiles < GRID_SM ? ntiles : GRID_SM;
    size_t smem_bytes = (size_t)SMEM_FLOATS * sizeof(float);
    cudaFuncSetAttribute(node_kernel, cudaFuncAttributeMaxDynamicSharedMemorySize,
                         (int)smem_bytes);
    node_kernel<<<grid_n, NTHREADS, smem_bytes>>>(hidden, out, n, ntiles);
}

// round 8
// speedup vs baseline: 1.2559x; 1.0341x over previous
#include <cuda_runtime.h>
#include <cuda_bf16.h>
#include <math.h>
#include <stdint.h>

#define MAXN 100000
#define D 64
#define K_PAD 208
#define C_TOT 256      // cols: [0:64) r, [64:128) i, [128:192) i_n, [192:256) h_n
#define TILE_N 64      // nodes per tile
#define NTHREADS 1024
#define GRID_SM 148
#define XSTR 68        // Xs row stride (64 nodes + 4 pad)

// smem partition (floats):
//  Mg [194][128] : 24832   gate cols 0-127, K rows 0-193
//  Mi [130][64]  : 8320    i_n cols 128-191, rows 0-127 then 192,193
//  Mh [64][64]   : 4096    h_n cols 192-255, rows 128-191
//  UB [16384]    : union — Xs[194][68] mainloop, Epi[64][256] epilogue
#define OFF_MG 0
#define OFF_MI 24832
#define OFF_MH 33152
#define OFF_UB 37248
#define SMEM_FLOATS 53632   // 214,528 bytes

// ---------------- scratch ----------------
__device__ float g_S[2 * (size_t)MAXN * D];
__device__ float g_s[2 * MAXN];
__device__ float g_M[K_PAD * C_TOT];
__device__ float g_bias[C_TOT];

// ---------------- kernel 1: precompute fused matrix ----------------
__global__ void precompute_kernel(const float* __restrict__ W_in, const float* __restrict__ b_in,
                                  const float* __restrict__ W_out, const float* __restrict__ b_out,
                                  const float* __restrict__ W_ih, const float* __restrict__ b_ih,
                                  const float* __restrict__ W_hh, const float* __restrict__ b_hh) {
    int k = blockIdx.x;
    int c = threadIdx.x;
    float v = 0.f;
    if (k < 64) {
        if (c < 192) {
            float a = 0.f;
            #pragma unroll 8
            for (int t = 0; t < 64; t++) a += W_in[k * 64 + t] * W_ih[t * 192 + c];
            v = a;
        }
    } else if (k < 128) {
        if (c < 192) {
            int aa = k - 64;
            float a = 0.f;
            #pragma unroll 8
            for (int t = 0; t < 64; t++) a += W_out[aa * 64 + t] * W_ih[(64 + t) * 192 + c];
            v = a;
        }
    } else if (k < 192) {
        int aa = k - 128;
        if (c < 128) v = W_hh[aa * 192 + c];
        else if (c >= 192) v = W_hh[aa * 192 + 128 + (c - 192)];
    } else if (k == 192) {
        if (c < 192) {
            float a = 0.f;
            for (int t = 0; t < 64; t++) a += b_in[t] * W_ih[t * 192 + c];
            v = a;
        }
    } else if (k == 193) {
        if (c < 192) {
            float a = 0.f;
            for (int t = 0; t < 64; t++) a += b_out[t] * W_ih[(64 + t) * 192 + c];
            v = a;
        }
    }
    g_M[k * C_TOT + c] = v;
    if (k == 0) {
        float b;
        if (c < 128)      b = b_ih[c] + b_hh[c];
        else if (c < 192) b = b_ih[c];
        else              b = b_hh[c - 64];
        g_bias[c] = b;
    }
}

// ---------------- kernel 2: zero accumulators ----------------
__global__ void zero_kernel(int n) {
    long totS = 2L * n * D;
    long tots = 2L * n;
    long tid = (long)blockIdx.x * blockDim.x + threadIdx.x;
    long stride = (long)gridDim.x * blockDim.x;
    float4 z = make_float4(0.f, 0.f, 0.f, 0.f);
    float4* S4 = reinterpret_cast<float4*>(g_S);
    for (long i = tid; i < totS / 4; i += stride) S4[i] = z;
    long rem = tots / 4;
    float4* s4 = reinterpret_cast<float4*>(g_s);
    for (long i = tid; i < rem; i += stride) s4[i] = z;
    for (long i = rem * 4 + tid; i < tots; i += stride) g_s[i] = 0.f;
}

// ---------------- kernel 3: edge scatter ----------------
__global__ void scatter_kernel(const float4* __restrict__ h4,
                               const int* __restrict__ srcA, const int* __restrict__ dstA,
                               const float* __restrict__ wA,
                               const int* __restrict__ srcB, const int* __restrict__ dstB,
                               const float* __restrict__ wB,
                               int E, int n) {
    int set = blockIdx.y;
    const int*   src = set ? srcB : srcA;
    const int*   dst = set ? dstB : dstA;
    const float* wp  = set ? wB   : wA;
    float* S  = g_S + (size_t)set * n * D;
    float* sw = g_s + (size_t)set * n;

    int lane = threadIdx.x & 31;
    int wid  = (blockIdx.x * blockDim.x + threadIdx.x) >> 5;
    int nw   = (gridDim.x * blockDim.x) >> 5;

    for (long base = (long)wid * 32; base < E; base += (long)nw * 32) {
        long e = base + lane;
        int s = 0, d = 0; float w = 0.f;
        if (e < E) { s = src[e]; d = dst[e]; w = wp[e]; }
        int cnt = (int)min((long)32, (long)E - base);
        for (int j = 0; j < cnt; j += 2) {
            int jj = j + (lane >> 4);
            float ww = __shfl_sync(0xffffffffu, w, jj);
            int   ss = __shfl_sync(0xffffffffu, s, jj);
            int   dd = __shfl_sync(0xffffffffu, d, jj);
            if (jj < cnt) {
                int l = lane & 15;
                float4 v = h4[(size_t)ss * 16 + l];
                float* p = S + (size_t)dd * D + l * 4;
                asm volatile("red.global.add.v4.f32 [%0], {%1,%2,%3,%4};"
                             :: "l"(p), "f"(v.x * ww), "f"(v.y * ww),
                                "f"(v.z * ww), "f"(v.w * ww) : "memory");
                if (l == 0)
                    asm volatile("red.global.add.f32 [%0], %1;"
                                 :: "l"(sw + dd), "f"(ww) : "memory");
            }
        }
    }
}

// ---------------- FMA micro-tile: 4 nodes x 4 cols ----------------
__device__ __forceinline__ void fma16(float acc[4][4], float4 x, float4 m) {
    acc[0][0]+=x.x*m.x; acc[0][1]+=x.x*m.y; acc[0][2]+=x.x*m.z; acc[0][3]+=x.x*m.w;
    acc[1][0]+=x.y*m.x; acc[1][1]+=x.y*m.y; acc[1][2]+=x.y*m.z; acc[1][3]+=x.y*m.w;
    acc[2][0]+=x.z*m.x; acc[2][1]+=x.z*m.y; acc[2][2]+=x.z*m.z; acc[2][3]+=x.z*m.w;
    acc[3][0]+=x.w*m.x; acc[3][1]+=x.w*m.y; acc[3][2]+=x.w*m.z; acc[3][3]+=x.w*m.w;
}

__device__ __forceinline__ float fsig(float x) {
    return 1.f / (1.f + __expf(-x));
}
__device__ __forceinline__ float ftanh(float x) {
    // tanh(x) = 2*sigmoid(2x) - 1
    return 2.f / (1.f + __expf(-2.f * x)) - 1.f;
}

// ---------------- kernel 4: persistent fused node GEMM + GRU ----------------
// 148 CTAs x 1024 threads, M resident in smem, 64-node tiles, barrier-free K-loop.
// Warps 0-15: gate cols (K=194); 16-23: i_n (K=130); 24-31: h_n (K=64).
// Per-SMSP K-work: 4*194 + 2*130 + 2*64 = 1164 k-steps (balanced).
extern __shared__ float smem[];

__global__ __launch_bounds__(NTHREADS, 1) void node_kernel(const float* __restrict__ hidden,
                                                           float* __restrict__ out,
                                                           int n_nodes, int ntiles) {
    float* Mg = smem + OFF_MG;   // [194][128]
    float* Mi = smem + OFF_MI;   // [130][64]
    float* Mh = smem + OFF_MH;   // [64][64]
    float* UB = smem + OFF_UB;   // Xs[194][68] / Epi[64][256]

    int tid = threadIdx.x;
    int wid = tid >> 5;
    int lane = tid & 31;

    // ---- load M panels once ----
    {
        float4* Mg4 = reinterpret_cast<float4*>(Mg);
        for (int i = tid; i < 194 * 32; i += NTHREADS) {
            int r = i >> 5, c4 = i & 31;
            Mg4[i] = *reinterpret_cast<const float4*>(&g_M[r * C_TOT + c4 * 4]);
        }
        float4* Mi4 = reinterpret_cast<float4*>(Mi);
        for (int i = tid; i < 130 * 16; i += NTHREADS) {
            int r = i >> 4, c4 = i & 15;
            int gr = (r < 128) ? r : (192 + (r - 128));
            Mi4[i] = *reinterpret_cast<const float4*>(&g_M[gr * C_TOT + 128 + c4 * 4]);
        }
        float4* Mh4 = reinterpret_cast<float4*>(Mh);
        for (int i = tid; i < 64 * 16; i += NTHREADS) {
            int r = i >> 4, c4 = i & 15;
            Mh4[i] = *reinterpret_cast<const float4*>(&g_M[(128 + r) * C_TOT + 192 + c4 * 4]);
        }
    }
    __syncthreads();

    const float* Sin  = g_S;
    const float* Sout = g_S + (size_t)n_nodes * D;

    // thread -> (colb, ng) mapping, fixed per thread
    int colb, ng;
    if (wid < 16)      { colb = lane * 4;                 ng = wid; }                     // gates
    else if (wid < 24) { colb = 128 + (lane & 15) * 4;    ng = (wid - 16) * 2 + (lane >> 4); } // i_n
    else               { colb = 192 + (lane & 15) * 4;    ng = (wid - 24) * 2 + (lane >> 4); } // h_n

    for (int tile = blockIdx.x; tile < ntiles; tile += gridDim.x) {
        int node0 = tile * TILE_N;

        // ---- build X tile: Xs[k][node], 16 threads per node ----
        {
            int g = tid >> 4;       // node 0..63
            int l = tid & 15;
            int n = node0 + g;
            bool nv = (n < n_nodes);
            #pragma unroll
            for (int k = l; k < 194; k += 16) {
                float v = 0.f;
                if (nv) {
                    if (k < 64)        v = Sin[(size_t)n * D + k];
                    else if (k < 128)  v = Sout[(size_t)n * D + (k - 64)];
                    else if (k < 192)  v = hidden[(size_t)n * D + (k - 128)];
                    else if (k == 192) v = g_s[n];
                    else               v = g_s[n_nodes + n];
                }
                UB[k * XSTR + g] = v;
            }
        }
        __syncthreads();

        // ---- barrier-free GEMM ----
        float acc[4][4];
        {
            float4 bv = *reinterpret_cast<const float4*>(&g_bias[colb]);
            #pragma unroll
            for (int i = 0; i < 4; i++) { acc[i][0]=bv.x; acc[i][1]=bv.y; acc[i][2]=bv.z; acc[i][3]=bv.w; }
        }

        if (wid < 16) {
            const float* xs = UB + ng * 4;
            const float* mp = Mg + colb;
            #pragma unroll 2
            for (int k = 0; k < 194; k++) {
                float4 m = *reinterpret_cast<const float4*>(mp + k * 128);
                float4 x = *reinterpret_cast<const float4*>(xs + k * XSTR);
                fma16(acc, x, m);
            }
        } else if (wid < 24) {
            const float* xs = UB + ng * 4;
            const float* mp = Mi + (colb - 128);
            #pragma unroll 2
            for (int k = 0; k < 130; k++) {
                int xk = (k < 128) ? k : (64 + k);   // 128->192, 129->193
                float4 m = *reinterpret_cast<const float4*>(mp + k * 64);
                float4 x = *reinterpret_cast<const float4*>(xs + xk * XSTR);
                fma16(acc, x, m);
            }
        } else {
            const float* xs = UB + ng * 4 + 128 * XSTR;
            const float* mp = Mh + (colb - 192);
            #pragma unroll 2
            for (int k = 0; k < 64; k++) {
                float4 m = *reinterpret_cast<const float4*>(mp + k * 64);
                float4 x = *reinterpret_cast<const float4*>(xs + k * XSTR);
                fma16(acc, x, m);
            }
        }
        __syncthreads();   // X no longer needed; UB becomes Epi

        // ---- write partials into Epi[64][256] ----
        #pragma unroll
        for (int i = 0; i < 4; i++) {
            *reinterpret_cast<float4*>(&UB[(ng * 4 + i) * C_TOT + colb]) =
                make_float4(acc[i][0], acc[i][1], acc[i][2], acc[i][3]);
        }
        __syncthreads();

        // ---- GRU: 64 nodes x 64 dims = 4096 outputs, 4 per thread ----
        #pragma unroll
        for (int j = 0; j < 4; j++) {
            int o = tid + j * NTHREADS;
            int i = o >> 6;
            int a = o & 63;
            int n = node0 + i;
            if (n < n_nodes) {
                float gr   = UB[i * C_TOT + a];
                float gi   = UB[i * C_TOT + 64 + a];
                float g_in = UB[i * C_TOT + 128 + a];
                float g_hn = UB[i * C_TOT + 192 + a];
                float r  = fsig(gr);
                float ig = fsig(gi);
                float newg = ftanh(g_in + r * g_hn);
                float h = hidden[(size_t)n * D + a];
                out[(size_t)n * D + a] = (1.f - ig) * h + ig * newg;
            }
        }
        __syncthreads();   // protect UB before next tile's X build
    }
}

// ---------------- launch ----------------
extern "C" void kernel_launch(void* const* d_in, const int* in_sizes, int n_in,
                              void* d_out, int out_size) {
    const float* hidden  = (const float*)d_in[0];
    const int*   in_src  = (const int*)  d_in[1];
    const int*   in_dst  = (const int*)  d_in[2];
    const float* in_w    = (const float*)d_in[3];
    const int*   out_src = (const int*)  d_in[4];
    const int*   out_dst = (const int*)  d_in[5];
    const float* out_w   = (const float*)d_in[6];
    const float* W_in    = (const float*)d_in[7];
    const float* b_in    = (const float*)d_in[8];
    const float* W_out   = (const float*)d_in[9];
    const float* b_out   = (const float*)d_in[10];
    const float* W_ih    = (const float*)d_in[11];
    const float* b_ih    = (const float*)d_in[12];
    const float* W_hh    = (const float*)d_in[13];
    const float* b_hh    = (const float*)d_in[14];
    float* out = (float*)d_out;

    int n = in_sizes[0] / D;
    if (n > MAXN) n = MAXN;
    int E = in_sizes[1];

    precompute_kernel<<<K_PAD, C_TOT>>>(W_in, b_in, W_out, b_out, W_ih, b_ih, W_hh, b_hh);
    zero_kernel<<<1184, 256>>>(n);
    if (E > 0) {
        dim3 grid(1184, 2);
        scatter_kernel<<<grid, 256>>>((const float4*)hidden,
                                      in_src, in_dst, in_w,
                                      out_src, out_dst, out_w, E, n);
    }

    int ntiles = (n + TILE_N - 1) / TILE_N;
    int grid_n = ntiles < GRID_SM ? ntiles : GRID_SM;
    size_t smem_bytes = (size_t)SMEM_FLOATS * sizeof(float);
    cudaFuncSetAttribute(node_kernel, cudaFuncAttributeMaxDynamicSharedMemorySize,
                         (int)smem_bytes);
    node_kernel<<<grid_n, NTHREADS, smem_bytes>>>(hidden, out, n, ntiles);
}